// round 16
// baseline (speedup 1.0000x reference)
#include <cuda_runtime.h>
#include <cstdint>

// BucketAdjustedHinge via fused piecewise-linear table, TMA bulk pipeline:
// cp.async.bulk stages x/bidx tiles into smem (async proxy, bypasses the
// per-thread LSU/L1tex request path), compute via conflict-free LDS.128 +
// table gather, output staged in smem and bulk-stored back. 3-stage
// mbarrier pipeline, 1024 elements/tile, 4 tiles/block, 1024 blocks.

#define NB 64
#define KK 20
#define TS 21
#define TABN (NB * TS)            // 1344
#define TPB 256
#define NEXACT 4194304
#define EB 1024                   // blocks (exact kernel)
#define TILE 1024                 // elements per tile (= TPB * 4)
#define NTILES 4                  // tiles per block
#define NSTAGE 3

__device__ __forceinline__ uint32_t s2u(const void* p) {
    return (uint32_t)__cvta_generic_to_shared(p);
}
__device__ __forceinline__ void mbar_init(uint32_t mb, uint32_t cnt) {
    asm volatile("mbarrier.init.shared.b64 [%0], %1;" :: "r"(mb), "r"(cnt) : "memory");
}
__device__ __forceinline__ void mbar_expect_tx(uint32_t mb, uint32_t bytes) {
    asm volatile("mbarrier.arrive.expect_tx.shared.b64 _, [%0], %1;"
                 :: "r"(mb), "r"(bytes) : "memory");
}
__device__ __forceinline__ void mbar_wait(uint32_t mb, uint32_t ph) {
    asm volatile(
        "{\n\t.reg .pred P;\n"
        "W%=:\n\t"
        "mbarrier.try_wait.parity.acquire.cta.shared::cta.b64 P, [%0], %1, 0x989680;\n\t"
        "@P bra D%=;\n\t"
        "bra W%=;\n"
        "D%=:\n\t}"
        :: "r"(mb), "r"(ph) : "memory");
}
__device__ __forceinline__ void bulk_ld(uint32_t smem, const void* g, uint32_t bytes,
                                        uint32_t mb) {
    asm volatile(
        "cp.async.bulk.shared::cluster.global.mbarrier::complete_tx::bytes "
        "[%0], [%1], %2, [%3];"
        :: "r"(smem), "l"(g), "r"(bytes), "r"(mb) : "memory");
}
__device__ __forceinline__ void bulk_st(void* g, uint32_t smem, uint32_t bytes) {
    asm volatile("cp.async.bulk.global.shared::cta.bulk_group [%0], [%1], %2;"
                 :: "l"(g), "r"(smem), "r"(bytes) : "memory");
}
__device__ __forceinline__ void bulk_commit() {
    asm volatile("cp.async.bulk.commit_group;" ::: "memory");
}
template <int N>
__device__ __forceinline__ void bulk_wait() {
    asm volatile("cp.async.bulk.wait_group %0;" :: "n"(N) : "memory");
}
__device__ __forceinline__ void fence_async_smem() {
    asm volatile("fence.proxy.async.shared::cta;" ::: "memory");
}

__device__ __forceinline__ void build_table(
        float2* tab,
        const float* __restrict__ base_knots, const float* __restrict__ base_w,
        const float* __restrict__ base_b,     const float* __restrict__ adj_knots,
        const float* __restrict__ adj_w,      const float* __restrict__ adj_b,
        int tid) {
    if (tid < NB) {
        const int b = tid;
        float cb   = __ldg(base_b) + __ldg(adj_b + b);
        float runW = 0.0f, runC = 0.0f;
        tab[b * TS] = make_float2(0.0f, cb);
#pragma unroll
        for (int j = 0; j < KK; ++j) {
            float bw = __ldg(base_w + j);
            float aw = __ldg(adj_w + b * KK + j);
            runW += bw + aw;
            runC = fmaf(bw, __ldg(base_knots + j), runC);
            runC = fmaf(aw, __ldg(adj_knots + b * KK + j), runC);
            tab[b * TS + j + 1] = make_float2(runW, cb - runC);
        }
    }
}

__device__ __forceinline__ float eval1(const float2* tab, float xf, int b,
                                       float ih, float c1) {
    int jp = __float2int_rd(fmaf(xf, ih, c1));
    jp = min(max(jp, 0), KK);
    float2 t = tab[b * TS + jp];
    return fmaf(t.x, xf, t.y);
}

struct SmemT {
    float2 tab[TABN];              // 10752 B (16B-aligned end)
    float  xs[NSTAGE][TILE];       // 3 x 4096 B
    int    bs[NSTAGE][TILE];       // 3 x 4096 B
    float  os[NSTAGE][TILE];       // 3 x 4096 B
    unsigned long long mbar[NSTAGE];
};                                 // ~47.6 KB static

__global__ void __launch_bounds__(TPB) bah_tma(
        const float* __restrict__ x,
        const int*   __restrict__ bidx,
        const float* __restrict__ base_knots,
        const float* __restrict__ base_w,
        const float* __restrict__ base_b,
        const float* __restrict__ adj_knots,
        const float* __restrict__ adj_w,
        const float* __restrict__ adj_b,
        float*       __restrict__ out) {
    __shared__ SmemT sm;
    const int tid = threadIdx.x;
    const int blk = blockIdx.x;

    uint32_t mb[NSTAGE];
#pragma unroll
    for (int s = 0; s < NSTAGE; ++s) mb[s] = s2u(&sm.mbar[s]);

    if (tid == 0) {
#pragma unroll
        for (int s = 0; s < NSTAGE; ++s) mbar_init(mb[s], 1);
        fence_async_smem();
        // issue first NSTAGE tile loads immediately
#pragma unroll
        for (int s = 0; s < NSTAGE; ++s) {
            const size_t e0 = (size_t)(blk + s * EB) * TILE;
            mbar_expect_tx(mb[s], TILE * 8);   // 4KB x + 4KB b
            bulk_ld(s2u(sm.xs[s]), x + e0,    TILE * 4, mb[s]);
            bulk_ld(s2u(sm.bs[s]), bidx + e0, TILE * 4, mb[s]);
        }
    }

    build_table(sm.tab, base_knots, base_w, base_b, adj_knots, adj_w, adj_b, tid);
    const float k0 = __ldg(base_knots);
    const float ih = (float)(KK - 1) / (__ldg(base_knots + KK - 1) - k0);
    const float c1 = 1.0f - k0 * ih;
    __syncthreads();   // table + mbarrier init visible to all

#pragma unroll
    for (int it = 0; it < NTILES; ++it) {
        const int slot = it % NSTAGE;
        const uint32_t ph = it / NSTAGE;       // each slot: phase 0 then 1
        mbar_wait(mb[slot], ph);

        if (it >= NSTAGE && tid == 0) bulk_wait<2>();   // os[slot] store drained
        if (it >= NSTAGE) __syncthreads();

        // compute: 4 contiguous elements per thread, conflict-free LDS.128
        float4 xv = ((const float4*)sm.xs[slot])[tid];
        int4   bv = ((const int4*)  sm.bs[slot])[tid];
        float4 o;
        o.x = eval1(sm.tab, xv.x, bv.x, ih, c1);
        o.y = eval1(sm.tab, xv.y, bv.y, ih, c1);
        o.z = eval1(sm.tab, xv.z, bv.z, ih, c1);
        o.w = eval1(sm.tab, xv.w, bv.w, ih, c1);
        ((float4*)sm.os[slot])[tid] = o;

        __syncthreads();                        // all STS done, xs consumed

        if (tid == 0) {
            const size_t e0 = (size_t)(blk + it * EB) * TILE;
            fence_async_smem();
            bulk_st(out + e0, s2u(sm.os[slot]), TILE * 4);
            bulk_commit();
            const int nt = it + NSTAGE;
            if (nt < NTILES) {
                const size_t ne = (size_t)(blk + nt * EB) * TILE;
                mbar_expect_tx(mb[slot], TILE * 8);
                bulk_ld(s2u(sm.xs[slot]), x + ne,    TILE * 4, mb[slot]);
                bulk_ld(s2u(sm.bs[slot]), bidx + ne, TILE * 4, mb[slot]);
            }
        }
    }
    if (tid == 0) bulk_wait<0>();               // drain output stores
}

// Generic fallback: persistent grid-stride (any n).
__global__ void __launch_bounds__(TPB) bah_generic(
        const float* __restrict__ x,  const int* __restrict__ bidx,
        const float* __restrict__ base_knots, const float* __restrict__ base_w,
        const float* __restrict__ base_b,     const float* __restrict__ adj_knots,
        const float* __restrict__ adj_w,      const float* __restrict__ adj_b,
        float* __restrict__ out, int n) {
    __shared__ float2 tab[TABN];
    const int tid = threadIdx.x;
    build_table(tab, base_knots, base_w, base_b, adj_knots, adj_w, adj_b, tid);
    const float k0 = __ldg(base_knots);
    const float ih = (float)(KK - 1) / (__ldg(base_knots + KK - 1) - k0);
    const float c1 = 1.0f - k0 * ih;
    __syncthreads();

    const int n4 = n >> 2;
    const int stride = gridDim.x * TPB;
    const float4* __restrict__ x4 = (const float4*)x;
    const int4*   __restrict__ b4 = (const int4*)bidx;
    float4*       __restrict__ o4 = (float4*)out;
    for (int idx = blockIdx.x * TPB + tid; idx < n4; idx += stride) {
        float4 xv = x4[idx];
        int4   bv = b4[idx];
        float4 o;
        o.x = eval1(tab, xv.x, bv.x, ih, c1);
        o.y = eval1(tab, xv.y, bv.y, ih, c1);
        o.z = eval1(tab, xv.z, bv.z, ih, c1);
        o.w = eval1(tab, xv.w, bv.w, ih, c1);
        o4[idx] = o;
    }
    if (blockIdx.x == 0) {
        for (int i = (n4 << 2) + tid; i < n; i += TPB)
            out[i] = eval1(tab, x[i], bidx[i], ih, c1);
    }
}

extern "C" void kernel_launch(void* const* d_in, const int* in_sizes, int n_in,
                              void* d_out, int out_size) {
    const float* x          = (const float*)d_in[0];
    const int*   bidx       = (const int*)  d_in[1];
    const float* base_knots = (const float*)d_in[2];
    const float* base_w     = (const float*)d_in[3];
    const float* base_b     = (const float*)d_in[4];
    const float* adj_knots  = (const float*)d_in[5];
    const float* adj_w      = (const float*)d_in[6];
    const float* adj_b      = (const float*)d_in[7];

    int n = in_sizes[0];

    if (n == NEXACT) {
        bah_tma<<<EB, TPB>>>(x, bidx, base_knots, base_w, base_b,
                             adj_knots, adj_w, adj_b, (float*)d_out);
    } else {
        int n4 = n >> 2;
        int blocks = 148 * 8;
        int needed = (n4 + TPB - 1) / TPB;
        if (needed < blocks) blocks = needed;
        if (blocks < 1) blocks = 1;
        bah_generic<<<blocks, TPB>>>(x, bidx, base_knots, base_w, base_b,
                                     adj_knots, adj_w, adj_b, (float*)d_out, n);
    }
}